// round 17
// baseline (speedup 1.0000x reference)
#include <cuda_runtime.h>
#include <cuda_bf16.h>
#include <math.h>
#include <float.h>
#include <stdint.h>

// GaussianQuantRegularizer2 — R16: mma.sync HMMA path with 3-group
// accumulator split. R15 was latency-bound (tensor 43%, issue 38%): each tile
// was one serial 6-MMA chain. Splitting into 3 independent groups
// (F1G1+F2G2 | F1G2+F2G1 | F1G3+F3G1) x 2 tiles = 6 chains of length 2.
// Same 6 terms, different fp32 add order (proven harmless: rel_err 0.0).
//
// Identities: zhat == prior[idx] (STE cancels), kl_loss == mean(kl2),
// argmax score == 16-dim dot f=[iv-1, mu*iv] . g_k=[-s^2/2, s].

#define THREADS 256            // 8 warps x 16 rows = 128 rows per CTA
#define NBLK    1024           // 131072 / 128
#define NCODES  1024
#define NTILE   (NCODES / 8)   // 128 code tiles of n=8

// smem layout (bytes)
#define SM_A1   0              // A splits: 128 rows x 16 bf16 = 4096 each
#define SM_A2   4096
#define SM_A3   8192
#define SM_B1   12288          // B splits: 1024 codes x 16 bf16 = 32768 each
#define SM_B2   45056
#define SM_B3   77824
#define SM_IDX  110592         // int idx[128]
#define SM_RED  111104         // float red[8]
#define SM_FLAG 111136
#define SM_TOTAL 111168

__device__ float g_partials[NBLK];
__device__ unsigned int g_done = 0;

static __device__ __forceinline__ void mma_bf16(float c[4],
        const uint32_t a[4], uint32_t b0, uint32_t b1) {
    asm volatile(
        "mma.sync.aligned.m16n8k16.row.col.f32.bf16.bf16.f32 "
        "{%0,%1,%2,%3}, {%4,%5,%6,%7}, {%8,%9}, {%0,%1,%2,%3};"
        : "+f"(c[0]), "+f"(c[1]), "+f"(c[2]), "+f"(c[3])
        : "r"(a[0]), "r"(a[1]), "r"(a[2]), "r"(a[3]), "r"(b0), "r"(b1));
}

static __device__ __forceinline__ void split3(float v, __nv_bfloat16& h1,
                                              __nv_bfloat16& h2, __nv_bfloat16& h3) {
    h1 = __float2bfloat16_rn(v);
    float r1 = v - __bfloat162float(h1);
    h2 = __float2bfloat16_rn(r1);
    float r2 = r1 - __bfloat162float(h2);
    h3 = __float2bfloat16_rn(r2);
}

static __device__ __forceinline__ void qmerge(float& b, int& i, int off) {
    float ob = __shfl_xor_sync(0xFFFFFFFFu, b, off);
    int   oi = __shfl_xor_sync(0xFFFFFFFFu, i, off);
    if (ob > b || (ob == b && oi < i)) { b = ob; i = oi; }
}

__global__ __launch_bounds__(THREADS, 2)
void gqr_mma(const float* __restrict__ z, const float* __restrict__ prior,
             float* __restrict__ out, int nrows, long long idx_off,
             long long kl_off, float scale)
{
    extern __shared__ char smem[];
    const int tid  = threadIdx.x;
    const int wid  = tid >> 5;
    const int lane = tid & 31;
    const int g    = lane >> 2;      // groupID (row within fragment)
    const int t4   = lane & 3;       // threadID_in_group

    // ---- codebook features -> 3-way bf16 split -> B1/B2/B3 (k-contiguous) --
    for (int e = tid; e < NCODES * 16; e += THREADS) {
        int c = e >> 4, k = e & 15;
        float s = prior[c * 8 + (k & 7)];
        float v = (k < 8) ? (-0.5f * s * s) : s;
        __nv_bfloat16 h1, h2, h3; split3(v, h1, h2, h3);
        uint32_t off = (uint32_t)(c * 32 + k * 2);
        *(__nv_bfloat16*)(smem + SM_B1 + off) = h1;
        *(__nv_bfloat16*)(smem + SM_B2 + off) = h2;
        *(__nv_bfloat16*)(smem + SM_B3 + off) = h3;
    }

    // ---- row features (threads 0..127, one row each) + KL ----
    float klacc = 0.0f;
    if (tid < 128) {
        int n  = blockIdx.x * 128 + tid;
        int bb = n >> 12, hw = n & 4095;
        const float* zp = z + ((size_t)bb << 16) + hw;
        #pragma unroll
        for (int d = 0; d < 8; d++) {
            float mu = zp[(size_t)d << 12];
            float lv = zp[(size_t)(8 + d) << 12];
            lv = fminf(fmaxf(lv, -30.0f), 20.0f);
            float var = expf(lv);
            float iv  = 1.0f / var;
            float fq  = iv - 1.0f;
            float fl  = mu * iv;
            klacc += mu * mu + var - 1.0f - lv;
            uint32_t oq = (uint32_t)(tid * 32 + d * 2);
            uint32_t ol = (uint32_t)(tid * 32 + (8 + d) * 2);
            __nv_bfloat16 h1, h2, h3;
            split3(fq, h1, h2, h3);
            *(__nv_bfloat16*)(smem + SM_A1 + oq) = h1;
            *(__nv_bfloat16*)(smem + SM_A2 + oq) = h2;
            *(__nv_bfloat16*)(smem + SM_A3 + oq) = h3;
            split3(fl, h1, h2, h3);
            *(__nv_bfloat16*)(smem + SM_A1 + ol) = h1;
            *(__nv_bfloat16*)(smem + SM_A2 + ol) = h2;
            *(__nv_bfloat16*)(smem + SM_A3 + ol) = h3;
        }
    }
    __syncthreads();

    // ---- A fragments (PTX m16n8k16 mapping), loaded once per warp ----
    const int R = wid * 16;
    uint32_t a1f[4], a2f[4], a3f[4];
    {
        uint32_t lo0 = (uint32_t)((R + g) * 32 + t4 * 4);
        uint32_t lo1 = (uint32_t)((R + g + 8) * 32 + t4 * 4);
        a1f[0] = *(const uint32_t*)(smem + SM_A1 + lo0);
        a1f[1] = *(const uint32_t*)(smem + SM_A1 + lo1);
        a1f[2] = *(const uint32_t*)(smem + SM_A1 + lo0 + 16);
        a1f[3] = *(const uint32_t*)(smem + SM_A1 + lo1 + 16);
        a2f[0] = *(const uint32_t*)(smem + SM_A2 + lo0);
        a2f[1] = *(const uint32_t*)(smem + SM_A2 + lo1);
        a2f[2] = *(const uint32_t*)(smem + SM_A2 + lo0 + 16);
        a2f[3] = *(const uint32_t*)(smem + SM_A2 + lo1 + 16);
        a3f[0] = *(const uint32_t*)(smem + SM_A3 + lo0);
        a3f[1] = *(const uint32_t*)(smem + SM_A3 + lo1);
        a3f[2] = *(const uint32_t*)(smem + SM_A3 + lo0 + 16);
        a3f[3] = *(const uint32_t*)(smem + SM_A3 + lo1 + 16);
    }

    // ---- main loop: 128 code tiles (n=8), 2 tiles x 3 accumulator groups ----
    float best0 = -FLT_MAX, best1 = -FLT_MAX;
    int   idx0 = 0, idx1 = 0;
    const uint32_t boff = (uint32_t)(g * 32 + t4 * 4);  // b0 addr within tile

    for (int ct = 0; ct < NTILE; ct += 2) {
        uint32_t o0 = (uint32_t)ct * 256 + boff;
        uint32_t o1 = o0 + 256;
        uint32_t x10 = *(const uint32_t*)(smem + SM_B1 + o0);
        uint32_t x11 = *(const uint32_t*)(smem + SM_B1 + o0 + 16);
        uint32_t x20 = *(const uint32_t*)(smem + SM_B2 + o0);
        uint32_t x21 = *(const uint32_t*)(smem + SM_B2 + o0 + 16);
        uint32_t x30 = *(const uint32_t*)(smem + SM_B3 + o0);
        uint32_t x31 = *(const uint32_t*)(smem + SM_B3 + o0 + 16);
        uint32_t y10 = *(const uint32_t*)(smem + SM_B1 + o1);
        uint32_t y11 = *(const uint32_t*)(smem + SM_B1 + o1 + 16);
        uint32_t y20 = *(const uint32_t*)(smem + SM_B2 + o1);
        uint32_t y21 = *(const uint32_t*)(smem + SM_B2 + o1 + 16);
        uint32_t y30 = *(const uint32_t*)(smem + SM_B3 + o1);
        uint32_t y31 = *(const uint32_t*)(smem + SM_B3 + o1 + 16);

        // 6 independent chains of length 2 (was: 2 chains of length 6)
        float cA1[4] = {0.f,0.f,0.f,0.f}, cA2[4] = {0.f,0.f,0.f,0.f};
        float cA3[4] = {0.f,0.f,0.f,0.f};
        float cB1[4] = {0.f,0.f,0.f,0.f}, cB2[4] = {0.f,0.f,0.f,0.f};
        float cB3[4] = {0.f,0.f,0.f,0.f};

        mma_bf16(cA1, a1f, x10, x11);   // F1G1
        mma_bf16(cB1, a1f, y10, y11);
        mma_bf16(cA2, a1f, x20, x21);   // F1G2
        mma_bf16(cB2, a1f, y20, y21);
        mma_bf16(cA3, a1f, x30, x31);   // F1G3
        mma_bf16(cB3, a1f, y30, y31);
        mma_bf16(cA1, a2f, x20, x21);   // +F2G2
        mma_bf16(cB1, a2f, y20, y21);
        mma_bf16(cA2, a2f, x10, x11);   // +F2G1
        mma_bf16(cB2, a2f, y10, y11);
        mma_bf16(cA3, a3f, x10, x11);   // +F3G1
        mma_bf16(cB3, a3f, y10, y11);

        float cA[4], cB[4];
        #pragma unroll
        for (int i = 0; i < 4; i++) {
            cA[i] = (cA1[i] + cA2[i]) + cA3[i];
            cB[i] = (cB1[i] + cB2[i]) + cB3[i];
        }

        // C mapping: c0 -> (row g, col 2t), c1 -> col 2t+1; c2,c3 -> row g+8
        int colA = ct * 8 + 2 * t4;
        int colB = colA + 8;
        bool q;
        q = cA[0] > best0; best0 = fmaxf(best0, cA[0]); idx0 = q ? colA     : idx0;
        q = cA[1] > best0; best0 = fmaxf(best0, cA[1]); idx0 = q ? colA + 1 : idx0;
        q = cA[2] > best1; best1 = fmaxf(best1, cA[2]); idx1 = q ? colA     : idx1;
        q = cA[3] > best1; best1 = fmaxf(best1, cA[3]); idx1 = q ? colA + 1 : idx1;
        q = cB[0] > best0; best0 = fmaxf(best0, cB[0]); idx0 = q ? colB     : idx0;
        q = cB[1] > best0; best0 = fmaxf(best0, cB[1]); idx0 = q ? colB + 1 : idx0;
        q = cB[2] > best1; best1 = fmaxf(best1, cB[2]); idx1 = q ? colB     : idx1;
        q = cB[3] > best1; best1 = fmaxf(best1, cB[3]); idx1 = q ? colB + 1 : idx1;
    }

    // ---- quad merge (cols are disjoint across the 4 lanes of a group) ----
    qmerge(best0, idx0, 1); qmerge(best0, idx0, 2);
    qmerge(best1, idx1, 1); qmerge(best1, idx1, 2);

    int* smidx = (int*)(smem + SM_IDX);
    if (t4 == 0) {
        smidx[R + g]     = idx0;     // row R+g
        smidx[R + g + 8] = idx1;     // row R+g+8
    }
    __syncwarp();

    // ---- outputs: zhat gather + indices (warp-local rows) ----
    {
        int r    = lane & 15;
        int half = lane >> 4;
        int n    = blockIdx.x * 128 + R + r;
        int bb   = n >> 12, hw = n & 4095;
        int mi   = smidx[R + r];
        if (half == 0) out[idx_off + n] = (float)mi;
        #pragma unroll
        for (int dd = 0; dd < 4; dd++) {
            int d = dd * 2 + half;
            out[(((size_t)(bb * 8 + d)) << 12) + hw] = prior[mi * 8 + d];
        }
    }

    // ---- KL block partial + fused last-block finalize ----
    #pragma unroll
    for (int o = 16; o > 0; o >>= 1)
        klacc += __shfl_down_sync(0xFFFFFFFFu, klacc, o);
    float* red   = (float*)(smem + SM_RED);
    int*   flagp = (int*)(smem + SM_FLAG);
    if (lane == 0) red[wid] = klacc;
    __syncthreads();
    if (tid == 0) {
        float s = 0.0f;
        #pragma unroll
        for (int i = 0; i < 8; i++) s += red[i];
        g_partials[blockIdx.x] = s;
        __threadfence();
        unsigned int old = atomicAdd(&g_done, 1u);
        *flagp = (old == (unsigned int)(NBLK - 1)) ? 1 : 0;
    }
    __syncthreads();
    if (*flagp) {
        __threadfence();
        float s = 0.0f;
        for (int i = tid; i < NBLK; i += THREADS) s += g_partials[i];
        #pragma unroll
        for (int o = 16; o > 0; o >>= 1)
            s += __shfl_down_sync(0xFFFFFFFFu, s, o);
        if (lane == 0) red[wid] = s;
        __syncthreads();
        if (tid == 0) {
            float acc = 0.0f;
            #pragma unroll
            for (int i = 0; i < 8; i++) acc += red[i];
            out[kl_off] = acc * scale;
            g_done = 0;
            __threadfence();
        }
    }
}

extern "C" void kernel_launch(void* const* d_in, const int* in_sizes, int n_in,
                              void* d_out, int out_size)
{
    const float* z     = (const float*)d_in[0];
    // d_in[1] (noise) is provably unused by the forward values.
    const float* prior = (const float*)d_in[2];
    float* out = (float*)d_out;

    int nrows = in_sizes[0] / 16;                       // 131072
    long long idx_off = (long long)out_size - (long long)nrows;
    if (idx_off < 1) idx_off = 1;
    long long kl_off  = idx_off - 1;

    float scale = (1.4426f * 0.5f) / (float)nrows;

    (void)cudaFuncSetAttribute(gqr_mma,
                               cudaFuncAttributeMaxDynamicSharedMemorySize, SM_TOTAL);
    gqr_mma<<<NBLK, THREADS, SM_TOTAL>>>(z, prior, out, nrows, idx_off,
                                         kl_off, scale);
}